// round 16
// baseline (speedup 1.0000x reference)
#include <cuda_runtime.h>
#include <cuda_fp16.h>
#include <math.h>
#include <stdint.h>

#define NTOK 8192
#define DDIM 1024
#define HDIM 4096
#define NEXP 8
#define NASSIGN (NTOK*2)

// ---------------- scratch (device globals; no allocation) ----------------
__device__ __half g_outb[(size_t)2 * NASSIGN * DDIM];       // split-K partials fp16
__device__ float  g_loadc[NTOK * NEXP];
__device__ int    g_route_e[NASSIGN];
__device__ float  g_route_g[NASSIGN];
__device__ int    g_counts[NEXP];
__device__ int    g_perm[NEXP * NTOK];
__device__ float  g_load[NEXP];
__device__ float  g_imp[NEXP];
__device__ __half g_xh[(size_t)NTOK * DDIM];                // x fp16
__device__ __half g_hh[(size_t)NASSIGN * HDIM];             // hidden fp16
__device__ __half g_w1t[(size_t)NEXP * HDIM * DDIM];        // W1^T [e][n][k]
__device__ __half g_w2t[(size_t)NEXP * DDIM * HDIM];        // W2^T [e][n][k]

// ---------------- helpers ----------------
__device__ __forceinline__ uint32_t smem_to_u32(const void* p) {
    uint32_t a;
    asm("{ .reg .u64 t; cvta.to.shared.u64 t, %1; cvt.u32.u64 %0, t; }" : "=r"(a) : "l"(p));
    return a;
}
__device__ __forceinline__ void ldsm4(uint32_t* r, uint32_t a) {
    asm volatile("ldmatrix.sync.aligned.m8n8.x4.shared.b16 {%0,%1,%2,%3}, [%4];"
        : "=r"(r[0]), "=r"(r[1]), "=r"(r[2]), "=r"(r[3]) : "r"(a));
}
__device__ __forceinline__ void hmma16816(float* c, const uint32_t* a, const uint32_t* b) {
    asm volatile("mma.sync.aligned.m16n8k16.row.col.f32.f16.f16.f32 "
        "{%0,%1,%2,%3}, {%4,%5,%6,%7}, {%8,%9}, {%0,%1,%2,%3};"
        : "+f"(c[0]), "+f"(c[1]), "+f"(c[2]), "+f"(c[3])
        : "r"(a[0]), "r"(a[1]), "r"(a[2]), "r"(a[3]), "r"(b[0]), "r"(b[1]));
}
#define CP_ASYNC16(dst, src, sz) \
    asm volatile("cp.async.cg.shared.global [%0], [%1], 16, %2;" \
        :: "r"(dst), "l"(src), "r"(sz) : "memory")
#define CP_COMMIT() asm volatile("cp.async.commit_group;" ::: "memory")
#define CP_WAIT2()  asm volatile("cp.async.wait_group 2;" ::: "memory")

// ---------------- zero counters ----------------
__global__ void zero_counts() {
    if (threadIdx.x < NEXP) g_counts[threadIdx.x] = 0;
}

// ---------------- gating ----------------
__global__ void gate_kernel(const float* __restrict__ x,
                            const float* __restrict__ noise,
                            const float* __restrict__ wg,
                            const float* __restrict__ wn) {
    int warp = threadIdx.x >> 5;
    int lane = threadIdx.x & 31;
    int n = blockIdx.x * 8 + warp;
    if (n >= NTOK) return;
    float ac[8] = {0,0,0,0,0,0,0,0};
    float an[8] = {0,0,0,0,0,0,0,0};
    const float* xr = x + (size_t)n * DDIM;
    for (int d = lane; d < DDIM; d += 32) {
        float xv = xr[d];
        const float4* wgp = (const float4*)(wg + (size_t)d * 8);
        const float4* wnp = (const float4*)(wn + (size_t)d * 8);
        float4 gA = wgp[0], gB = wgp[1];
        float4 nA = wnp[0], nB = wnp[1];
        ac[0] += xv * gA.x; ac[1] += xv * gA.y; ac[2] += xv * gA.z; ac[3] += xv * gA.w;
        ac[4] += xv * gB.x; ac[5] += xv * gB.y; ac[6] += xv * gB.z; ac[7] += xv * gB.w;
        an[0] += xv * nA.x; an[1] += xv * nA.y; an[2] += xv * nA.z; an[3] += xv * nA.w;
        an[4] += xv * nB.x; an[5] += xv * nB.y; an[6] += xv * nB.z; an[7] += xv * nB.w;
    }
    #pragma unroll
    for (int off = 16; off; off >>= 1)
        #pragma unroll
        for (int e = 0; e < 8; e++) {
            ac[e] += __shfl_xor_sync(0xffffffffu, ac[e], off);
            an[e] += __shfl_xor_sync(0xffffffffu, an[e], off);
        }
    if (lane == 0) {
        float clean[8], sd[8], nz[8];
        #pragma unroll
        for (int e = 0; e < 8; e++) {
            clean[e] = ac[e];
            float z = an[e];
            float sp = fmaxf(z, 0.0f) + log1pf(expf(-fabsf(z)));
            sd[e] = sp + 0.01f;
            nz[e] = clean[e] + noise[(size_t)n * 8 + e] * sd[e];
        }
        int i0 = 0, i1 = -1;
        float v0 = nz[0], v1 = -INFINITY, v2 = -INFINITY;
        #pragma unroll
        for (int e = 1; e < 8; e++) {
            float v = nz[e];
            if (v > v0)      { v2 = v1; v1 = v0; i1 = i0; v0 = v; i0 = e; }
            else if (v > v1) { v2 = v1; v1 = v;  i1 = e; }
            else if (v > v2) { v2 = v; }
        }
        float t = expf(v1 - v0);
        float gate0 = 1.0f / (1.0f + t);
        float gate1 = t / (1.0f + t);
        #pragma unroll
        for (int e = 0; e < 8; e++) {
            bool is_in = nz[e] > v2;
            float thr = is_in ? v2 : v1;
            g_loadc[(size_t)n * 8 + e] = normcdff((clean[e] - thr) / sd[e]);
        }
        g_route_e[2 * n]     = i0;  g_route_g[2 * n]     = gate0;
        g_route_e[2 * n + 1] = i1;  g_route_g[2 * n + 1] = gate1;
        int p0 = atomicAdd(&g_counts[i0], 1);
        g_perm[i0 * NTOK + p0] = 2 * n;
        int p1 = atomicAdd(&g_counts[i1], 1);
        g_perm[i1 * NTOK + p1] = 2 * n + 1;
    }
}

__global__ void reduce_kernel() {
    int e = blockIdx.x;
    int t = threadIdx.x;
    float sl = 0.0f, si = 0.0f;
    for (int n = t; n < NTOK; n += 256) sl += g_loadc[(size_t)n * 8 + e];
    for (int a = t; a < NASSIGN; a += 256)
        if (g_route_e[a] == e) si += g_route_g[a];
    __shared__ float shl[256], shi[256];
    shl[t] = sl; shi[t] = si;
    __syncthreads();
    for (int off = 128; off; off >>= 1) {
        if (t < off) { shl[t] += shl[t + off]; shi[t] += shi[t + off]; }
        __syncthreads();
    }
    if (t == 0) { g_load[e] = shl[0]; g_imp[e] = shi[0]; }
}

__global__ void loss_kernel(float* __restrict__ out) {
    if (threadIdx.x != 0 || blockIdx.x != 0) return;
    float mi = 0.0f, ml = 0.0f;
    for (int e = 0; e < NEXP; e++) { mi += g_imp[e]; ml += g_load[e]; }
    mi *= (1.0f / NEXP); ml *= (1.0f / NEXP);
    float vi = 0.0f, vl = 0.0f;
    for (int e = 0; e < NEXP; e++) {
        float di = g_imp[e] - mi;  vi += di * di;
        float dl = g_load[e] - ml; vl += dl * dl;
    }
    vi *= (1.0f / (NEXP - 1)); vl *= (1.0f / (NEXP - 1));
    out[0] = (vi / (mi * mi + 1e-10f) + vl / (ml * ml + 1e-10f)) * 0.01f;
}

// ---------------- x fp32 -> fp16 ----------------
__global__ void convert_x(const float4* __restrict__ src, uint2* __restrict__ dst, size_t n4) {
    size_t stride = (size_t)gridDim.x * blockDim.x;
    for (size_t i = (size_t)blockIdx.x * blockDim.x + threadIdx.x; i < n4; i += stride) {
        float4 v = src[i];
        __half2 a = __floats2half2_rn(v.x, v.y);
        __half2 b = __floats2half2_rn(v.z, v.w);
        uint2 o;
        memcpy(&o.x, &a, 4); memcpy(&o.y, &b, 4);
        dst[i] = o;
    }
}

// ---------------- weight fp32 [e][K][N] -> fp16 transposed [e][N][K] (vectorized) --
__global__ void convert_w_v2(const float* __restrict__ W, __half* __restrict__ Wt,
                             int K, int N) {
    __shared__ float tile[32][129];
    int e = blockIdx.z;
    int k0 = blockIdx.x * 32, n0 = blockIdx.y * 128;
    int t = threadIdx.x;
    const float* Wp = W + (size_t)e * K * N + (size_t)k0 * N + n0;

    int lrow = t >> 3, lc4 = t & 7;
    #pragma unroll
    for (int i = 0; i < 4; i++) {
        float4 v = *(const float4*)(Wp + (size_t)lrow * N + i * 32 + lc4 * 4);
        tile[lrow][i * 32 + lc4 * 4 + 0] = v.x;
        tile[lrow][i * 32 + lc4 * 4 + 1] = v.y;
        tile[lrow][i * 32 + lc4 * 4 + 2] = v.z;
        tile[lrow][i * 32 + lc4 * 4 + 3] = v.w;
    }
    __syncthreads();

    __half* outp = Wt + ((size_t)e * N + n0) * K + k0;
    #pragma unroll
    for (int j = 0; j < 2; j++) {
        int idx = t + j * 256;
        int n = idx >> 2, kb = idx & 3;
        uint32_t h[4];
        #pragma unroll
        for (int p = 0; p < 4; p++) {
            float lo = tile[kb * 8 + p * 2 + 0][n];
            float hi = tile[kb * 8 + p * 2 + 1][n];
            __half2 hv = __floats2half2_rn(lo, hi);
            memcpy(&h[p], &hv, 4);
        }
        uint4 o = make_uint4(h[0], h[1], h[2], h[3]);
        *(uint4*)(outp + (size_t)n * K + kb * 8) = o;
    }
}

// ---------------- fp16 grouped expert GEMM ----------------
// CTA tile 128 x 256, k-chunk 64, 8 warps (2m x 4n), warp tile 64x64,
// 4-stage cp.async pipe. GEMM2 split-K=2 (KSPLIT template param).
#define NSTAGE 4
#define STG (16384u + 256u * 128u)
#define GEMM_SMEM (NSTAGE * (16384 + 256 * 128))

template <int WHICH, int KSPLIT>
__global__ __launch_bounds__(256, 1) void moe_gemm_f16(const float* __restrict__ bias) {
    constexpr int KD = WHICH ? HDIM : DDIM;      // full k extent of source rows
    constexpr int KSEG = KD / KSPLIT;            // k extent this CTA covers
    constexpr int NC = WHICH ? DDIM : HDIM;
    constexpr int NST = KSEG / 64;

    const int e = blockIdx.z & (NEXP - 1);
    const int kh = blockIdx.z >> 3;              // 0 for KSPLIT=1
    const int count = g_counts[e];
    const int m0 = blockIdx.y * 128;
    if (m0 >= count) return;
    const int c0 = blockIdx.x * 256;
    const size_t khoff = (size_t)kh * KSEG * 2;  // byte offset into k

    extern __shared__ char smem[];
    __shared__ int s_a[128];
    const uint32_t sb = smem_to_u32(smem);
    const int t = threadIdx.x;
    const int lane = t & 31, wid = t >> 5;
    const int wm = wid & 1, wn = wid >> 1;

    if (t < 128) {
        int m = m0 + t;
        s_a[t] = (m < count) ? g_perm[e * NTOK + m] : -1;
    }
    __syncthreads();

    const char* Ab = (const char*)(WHICH ? g_hh : g_xh);
    const char* Bb = (const char*)((WHICH ? g_w2t : g_w1t) + ((size_t)e * NC + c0) * KD);

    const char* sA[4]; uint32_t adst[4]; int asz[4];
    #pragma unroll
    for (int i = 0; i < 4; i++) {
        int u = t + 256 * i;
        int r = u >> 3, c = u & 7;
        int a = s_a[r];
        int rowi = (a < 0) ? 0 : (WHICH ? a : (a >> 1));
        sA[i] = Ab + ((size_t)rowi * KD) * 2 + khoff + c * 16;
        asz[i] = (a < 0) ? 0 : 16;
        adst[i] = r * 128 + (((uint32_t)(c ^ (r & 7))) << 4);
    }
    const char* sB[8]; uint32_t bdst[8];
    #pragma unroll
    for (int i = 0; i < 8; i++) {
        int u = t + 256 * i;
        int r = u >> 3, c = u & 7;
        sB[i] = Bb + ((size_t)r * KD) * 2 + khoff + c * 16;
        bdst[i] = 16384u + r * 128 + (((uint32_t)(c ^ (r & 7))) << 4);
    }

    auto load_stage = [&](int s) {
        uint32_t base = sb + (uint32_t)(s & (NSTAGE - 1)) * STG;
        int koff = s * 128;
        #pragma unroll
        for (int i = 0; i < 4; i++)
            CP_ASYNC16(base + adst[i], sA[i] + koff, asz[i]);
        #pragma unroll
        for (int i = 0; i < 8; i++)
            CP_ASYNC16(base + bdst[i], sB[i] + koff, 16);
        CP_COMMIT();
    };

    uint32_t aoff[4];
    #pragma unroll
    for (int mi = 0; mi < 4; mi++) {
        int row = wm * 64 + mi * 16 + (lane & 15);
        int c = lane >> 4;
        aoff[mi] = row * 128 + (((uint32_t)(c ^ (row & 7))) << 4);
    }
    uint32_t boff[4];
    #pragma unroll
    for (int p = 0; p < 4; p++) {
        int g = lane >> 3;
        int row = wn * 64 + p * 16 + (g >> 1) * 8 + (lane & 7);
        int c = g & 1;
        boff[p] = 16384u + row * 128 + (((uint32_t)(c ^ (row & 7))) << 4);
    }

    float acc[4][8][4];
    #pragma unroll
    for (int i = 0; i < 4; i++)
        #pragma unroll
        for (int j = 0; j < 8; j++)
            #pragma unroll
            for (int k = 0; k < 4; k++) acc[i][j][k] = 0.0f;

    load_stage(0);
    load_stage(1);
    load_stage(2);

    for (int s = 0; s < NST; s++) {
        CP_WAIT2();
        __syncthreads();
        if (s + 3 < NST) load_stage(s + 3);
        else CP_COMMIT();
        uint32_t ab = sb + (uint32_t)(s & (NSTAGE - 1)) * STG;
        #pragma unroll
        for (int ks = 0; ks < 4; ks++) {
            const uint32_t kx = (uint32_t)ks << 5;
            uint32_t Af[4][4], Bf[4][4];
            #pragma unroll
            for (int mi = 0; mi < 4; mi++) ldsm4(Af[mi], ab + (aoff[mi] ^ kx));
            #pragma unroll
            for (int p = 0; p < 4; p++)    ldsm4(Bf[p], ab + (boff[p] ^ kx));
            #pragma unroll
            for (int p = 0; p < 4; p++)
                #pragma unroll
                for (int half = 0; half < 2; half++) {
                    int n = p * 2 + half;
                    #pragma unroll
                    for (int mi = 0; mi < 4; mi++)
                        hmma16816(acc[mi][n], Af[mi], &Bf[p][half * 2]);
                }
        }
    }

    // ---- epilogue ----
    const float bsel = (kh == 0) ? 1.0f : 0.0f;   // bias only in partial 0
    const float* bias_e = bias + (size_t)e * NC + c0;
    int colb = wn * 64 + (lane & 3) * 2;
    float2 bv[8];
    #pragma unroll
    for (int n = 0; n < 8; n++) {
        float2 b = *(const float2*)(bias_e + colb + n * 8);
        bv[n] = make_float2(b.x * bsel, b.y * bsel);
    }

    __half* OutB = g_outb + (size_t)kh * NASSIGN * DDIM;
    #pragma unroll
    for (int mi = 0; mi < 4; mi++) {
        #pragma unroll
        for (int half = 0; half < 2; half++) {
            int r = wm * 64 + mi * 16 + (lane >> 2) + half * 8;
            int a = s_a[r];
            if (a >= 0) {
                #pragma unroll
                for (int n = 0; n < 8; n++) {
                    float v0 = acc[mi][n][half * 2 + 0] + bv[n].x;
                    float v1 = acc[mi][n][half * 2 + 1] + bv[n].y;
                    size_t col = (size_t)c0 + colb + n * 8;
                    if (WHICH == 0) {
                        v0 = fmaxf(v0, 0.0f); v1 = fmaxf(v1, 0.0f);
                        *(__half2*)(g_hh + (size_t)a * HDIM + col) = __floats2half2_rn(v0, v1);
                    } else {
                        *(__half2*)(OutB + (size_t)a * DDIM + col) = __floats2half2_rn(v0, v1);
                    }
                }
            }
        }
    }
}

// ---------------- combine (sum 2 fp16 partials per assignment -> fp32 y) --------
__global__ void combine_kernel(float* __restrict__ y) {
    int n = blockIdx.x;
    int t = threadIdx.x;
    float gate0 = g_route_g[2 * n];
    float gate1 = g_route_g[2 * n + 1];
    const __half* P0 = g_outb;
    const __half* P1 = g_outb + (size_t)NASSIGN * DDIM;
    const uint2* a0p = (const uint2*)(P0 + (size_t)(2 * n) * DDIM);
    const uint2* a1p = (const uint2*)(P1 + (size_t)(2 * n) * DDIM);
    const uint2* b0p = (const uint2*)(P0 + (size_t)(2 * n + 1) * DDIM);
    const uint2* b1p = (const uint2*)(P1 + (size_t)(2 * n + 1) * DDIM);
    float4* yp = (float4*)(y + (size_t)n * DDIM);
    uint2 a0 = a0p[t], a1 = a1p[t], b0 = b0p[t], b1 = b1p[t];
    __half2 h;
    float2 fa0, fa1, fa2, fa3, fb0, fb1, fb2, fb3;
    memcpy(&h, &a0.x, 4); fa0 = __half22float2(h);
    memcpy(&h, &a0.y, 4); fa1 = __half22float2(h);
    memcpy(&h, &a1.x, 4); fa2 = __half22float2(h);
    memcpy(&h, &a1.y, 4); fa3 = __half22float2(h);
    memcpy(&h, &b0.x, 4); fb0 = __half22float2(h);
    memcpy(&h, &b0.y, 4); fb1 = __half22float2(h);
    memcpy(&h, &b1.x, 4); fb2 = __half22float2(h);
    memcpy(&h, &b1.y, 4); fb3 = __half22float2(h);
    yp[t] = make_float4(
        gate0 * (fa0.x + fa2.x) + gate1 * (fb0.x + fb2.x),
        gate0 * (fa0.y + fa2.y) + gate1 * (fb0.y + fb2.y),
        gate0 * (fa1.x + fa3.x) + gate1 * (fb1.x + fb3.x),
        gate0 * (fa1.y + fa3.y) + gate1 * (fb1.y + fb3.y));
}

// ---------------- launch ----------------
extern "C" void kernel_launch(void* const* d_in, const int* in_sizes, int n_in,
                              void* d_out, int out_size) {
    (void)in_sizes; (void)n_in; (void)out_size;
    const float* x  = (const float*)d_in[0];
    const float* nz = (const float*)d_in[1];
    const float* wg = (const float*)d_in[2];
    const float* wn = (const float*)d_in[3];
    const float* W1 = (const float*)d_in[4];
    const float* b1 = (const float*)d_in[5];
    const float* W2 = (const float*)d_in[6];
    const float* b2 = (const float*)d_in[7];
    float* y = (float*)d_out;

    cudaFuncSetAttribute((const void*)moe_gemm_f16<0, 1>,
                         cudaFuncAttributeMaxDynamicSharedMemorySize, GEMM_SMEM);
    cudaFuncSetAttribute((const void*)moe_gemm_f16<1, 2>,
                         cudaFuncAttributeMaxDynamicSharedMemorySize, GEMM_SMEM);

    void *xh, *w1t, *w2t;
    cudaGetSymbolAddress(&xh, g_xh);
    cudaGetSymbolAddress(&w1t, g_w1t);
    cudaGetSymbolAddress(&w2t, g_w2t);

    zero_counts<<<1, 32>>>();
    gate_kernel<<<NTOK / 8, 256>>>(x, nz, wg, wn);
    reduce_kernel<<<NEXP, 256>>>();
    loss_kernel<<<1, 1>>>(y + (size_t)NTOK * DDIM);

    convert_x<<<1024, 256>>>((const float4*)x, (uint2*)xh, (size_t)NTOK * DDIM / 4);
    convert_w_v2<<<dim3(DDIM / 32, HDIM / 128, NEXP), 256>>>(W1, (__half*)w1t, DDIM, HDIM);
    convert_w_v2<<<dim3(HDIM / 32, DDIM / 128, NEXP), 256>>>(W2, (__half*)w2t, HDIM, DDIM);

    moe_gemm_f16<0, 1><<<dim3(HDIM / 256, NASSIGN / 128, NEXP), 256, GEMM_SMEM>>>(b1);
    moe_gemm_f16<1, 2><<<dim3(DDIM / 256, NASSIGN / 128, NEXP * 2), 256, GEMM_SMEM>>>(b2);
    combine_kernel<<<NTOK, 256>>>(y);
}

// round 17
// speedup vs baseline: 1.0265x; 1.0265x over previous
#include <cuda_runtime.h>
#include <cuda_fp16.h>
#include <math.h>
#include <stdint.h>

#define NTOK 8192
#define DDIM 1024
#define HDIM 4096
#define NEXP 8
#define NASSIGN (NTOK*2)

// ---------------- scratch (device globals; no allocation) ----------------
__device__ __half g_outb[(size_t)NASSIGN * DDIM];           // expert outputs fp16
__device__ float  g_loadc[NTOK * NEXP];
__device__ int    g_route_e[NASSIGN];
__device__ float  g_route_g[NASSIGN];
__device__ int    g_counts[NEXP];
__device__ int    g_perm[NEXP * NTOK];
__device__ float  g_load[NEXP];
__device__ float  g_imp[NEXP];
__device__ __half g_xh[(size_t)NTOK * DDIM];                // x fp16
__device__ __half g_hh[(size_t)NASSIGN * HDIM];             // hidden fp16
__device__ __half g_w1t[(size_t)NEXP * HDIM * DDIM];        // W1^T [e][n][k]
__device__ __half g_w2t[(size_t)NEXP * DDIM * HDIM];        // W2^T [e][n][k]

// ---------------- helpers ----------------
__device__ __forceinline__ uint32_t smem_to_u32(const void* p) {
    uint32_t a;
    asm("{ .reg .u64 t; cvta.to.shared.u64 t, %1; cvt.u32.u64 %0, t; }" : "=r"(a) : "l"(p));
    return a;
}
__device__ __forceinline__ void ldsm4(uint32_t* r, uint32_t a) {
    asm volatile("ldmatrix.sync.aligned.m8n8.x4.shared.b16 {%0,%1,%2,%3}, [%4];"
        : "=r"(r[0]), "=r"(r[1]), "=r"(r[2]), "=r"(r[3]) : "r"(a));
}
__device__ __forceinline__ void hmma16816(float* c, const uint32_t* a, const uint32_t* b) {
    asm volatile("mma.sync.aligned.m16n8k16.row.col.f32.f16.f16.f32 "
        "{%0,%1,%2,%3}, {%4,%5,%6,%7}, {%8,%9}, {%0,%1,%2,%3};"
        : "+f"(c[0]), "+f"(c[1]), "+f"(c[2]), "+f"(c[3])
        : "r"(a[0]), "r"(a[1]), "r"(a[2]), "r"(a[3]), "r"(b[0]), "r"(b[1]));
}
#define CP_ASYNC16(dst, src, sz) \
    asm volatile("cp.async.cg.shared.global [%0], [%1], 16, %2;" \
        :: "r"(dst), "l"(src), "r"(sz) : "memory")
#define CP_COMMIT() asm volatile("cp.async.commit_group;" ::: "memory")
#define CP_WAIT2()  asm volatile("cp.async.wait_group 2;" ::: "memory")

// ---------------- zero counters ----------------
__global__ void zero_counts() {
    if (threadIdx.x < NEXP) g_counts[threadIdx.x] = 0;
}

// ---------------- fused prep: gate | convert W1 | convert W2 | convert x --------
// block roles by blockIdx.x:
//   [0, 1024)          gate (8 tokens per block)
//   [1024, 9216)       convert_w (W1: K=DDIM, N=HDIM) -> g_w1t
//   [9216, 17408)      convert_w (W2: K=HDIM, N=DDIM) -> g_w2t
//   [17408, 18432)     convert_x
#define GATE_BLKS 1024
#define CW1_BLKS  (NEXP * (DDIM / 32) * (HDIM / 128))   // 8192
#define CW2_BLKS  (NEXP * (HDIM / 32) * (DDIM / 128))   // 8192
#define CX_BLKS   1024
#define PREP_BLKS (GATE_BLKS + CW1_BLKS + CW2_BLKS + CX_BLKS)

__device__ __forceinline__ void convert_w_block(const float* __restrict__ W,
                                                __half* __restrict__ Wt,
                                                int K, int N, int bi,
                                                float (*tile)[129]) {
    int nkx = K / 32;
    int kxi = bi % nkx;
    int rest = bi / nkx;
    int nyi = rest % (N / 128);
    int e = rest / (N / 128);
    int k0 = kxi * 32, n0 = nyi * 128;
    int t = threadIdx.x;
    const float* Wp = W + (size_t)e * K * N + (size_t)k0 * N + n0;

    int lrow = t >> 3, lc4 = t & 7;
    #pragma unroll
    for (int i = 0; i < 4; i++) {
        float4 v = *(const float4*)(Wp + (size_t)lrow * N + i * 32 + lc4 * 4);
        tile[lrow][i * 32 + lc4 * 4 + 0] = v.x;
        tile[lrow][i * 32 + lc4 * 4 + 1] = v.y;
        tile[lrow][i * 32 + lc4 * 4 + 2] = v.z;
        tile[lrow][i * 32 + lc4 * 4 + 3] = v.w;
    }
    __syncthreads();

    __half* outp = Wt + ((size_t)e * N + n0) * K + k0;
    #pragma unroll
    for (int j = 0; j < 2; j++) {
        int idx = t + j * 256;
        int n = idx >> 2, kb = idx & 3;
        uint32_t h[4];
        #pragma unroll
        for (int p = 0; p < 4; p++) {
            float lo = tile[kb * 8 + p * 2 + 0][n];
            float hi = tile[kb * 8 + p * 2 + 1][n];
            __half2 hv = __floats2half2_rn(lo, hi);
            memcpy(&h[p], &hv, 4);
        }
        uint4 o = make_uint4(h[0], h[1], h[2], h[3]);
        *(uint4*)(outp + (size_t)n * K + kb * 8) = o;
    }
}

__global__ __launch_bounds__(256) void prep_kernel(const float* __restrict__ x,
                                                   const float* __restrict__ noise,
                                                   const float* __restrict__ wg,
                                                   const float* __restrict__ wn,
                                                   const float* __restrict__ W1,
                                                   const float* __restrict__ W2) {
    __shared__ float tile[32][129];
    int b = blockIdx.x;

    if (b < GATE_BLKS) {
        // ---- gate role ----
        int warp = threadIdx.x >> 5;
        int lane = threadIdx.x & 31;
        int n = b * 8 + warp;
        if (n >= NTOK) return;
        float ac[8] = {0,0,0,0,0,0,0,0};
        float an[8] = {0,0,0,0,0,0,0,0};
        const float* xr = x + (size_t)n * DDIM;
        for (int d = lane; d < DDIM; d += 32) {
            float xv = xr[d];
            const float4* wgp = (const float4*)(wg + (size_t)d * 8);
            const float4* wnp = (const float4*)(wn + (size_t)d * 8);
            float4 gA = wgp[0], gB = wgp[1];
            float4 nA = wnp[0], nB = wnp[1];
            ac[0] += xv * gA.x; ac[1] += xv * gA.y; ac[2] += xv * gA.z; ac[3] += xv * gA.w;
            ac[4] += xv * gB.x; ac[5] += xv * gB.y; ac[6] += xv * gB.z; ac[7] += xv * gB.w;
            an[0] += xv * nA.x; an[1] += xv * nA.y; an[2] += xv * nA.z; an[3] += xv * nA.w;
            an[4] += xv * nB.x; an[5] += xv * nB.y; an[6] += xv * nB.z; an[7] += xv * nB.w;
        }
        #pragma unroll
        for (int off = 16; off; off >>= 1)
            #pragma unroll
            for (int e = 0; e < 8; e++) {
                ac[e] += __shfl_xor_sync(0xffffffffu, ac[e], off);
                an[e] += __shfl_xor_sync(0xffffffffu, an[e], off);
            }
        if (lane == 0) {
            float clean[8], sd[8], nz[8];
            #pragma unroll
            for (int e = 0; e < 8; e++) {
                clean[e] = ac[e];
                float z = an[e];
                float sp = fmaxf(z, 0.0f) + log1pf(expf(-fabsf(z)));
                sd[e] = sp + 0.01f;
                nz[e] = clean[e] + noise[(size_t)n * 8 + e] * sd[e];
            }
            int i0 = 0, i1 = -1;
            float v0 = nz[0], v1 = -INFINITY, v2 = -INFINITY;
            #pragma unroll
            for (int e = 1; e < 8; e++) {
                float v = nz[e];
                if (v > v0)      { v2 = v1; v1 = v0; i1 = i0; v0 = v; i0 = e; }
                else if (v > v1) { v2 = v1; v1 = v;  i1 = e; }
                else if (v > v2) { v2 = v; }
            }
            float t = expf(v1 - v0);
            float gate0 = 1.0f / (1.0f + t);
            float gate1 = t / (1.0f + t);
            #pragma unroll
            for (int e = 0; e < 8; e++) {
                bool is_in = nz[e] > v2;
                float thr = is_in ? v2 : v1;
                g_loadc[(size_t)n * 8 + e] = normcdff((clean[e] - thr) / sd[e]);
            }
            g_route_e[2 * n]     = i0;  g_route_g[2 * n]     = gate0;
            g_route_e[2 * n + 1] = i1;  g_route_g[2 * n + 1] = gate1;
            int p0 = atomicAdd(&g_counts[i0], 1);
            g_perm[i0 * NTOK + p0] = 2 * n;
            int p1 = atomicAdd(&g_counts[i1], 1);
            g_perm[i1 * NTOK + p1] = 2 * n + 1;
        }
    } else if (b < GATE_BLKS + CW1_BLKS) {
        convert_w_block(W1, g_w1t, DDIM, HDIM, b - GATE_BLKS, tile);
    } else if (b < GATE_BLKS + CW1_BLKS + CW2_BLKS) {
        convert_w_block(W2, g_w2t, HDIM, DDIM, b - GATE_BLKS - CW1_BLKS, tile);
    } else {
        // ---- convert_x role ----
        int bi = b - GATE_BLKS - CW1_BLKS - CW2_BLKS;
        const float4* src = (const float4*)x;
        uint2* dst = (uint2*)g_xh;
        size_t n4 = (size_t)NTOK * DDIM / 4;
        size_t stride = (size_t)CX_BLKS * 256;
        for (size_t i = (size_t)bi * 256 + threadIdx.x; i < n4; i += stride) {
            float4 v = src[i];
            __half2 a = __floats2half2_rn(v.x, v.y);
            __half2 c = __floats2half2_rn(v.z, v.w);
            uint2 o;
            memcpy(&o.x, &a, 4); memcpy(&o.y, &c, 4);
            dst[i] = o;
        }
    }
}

__global__ void reduce_kernel() {
    int e = blockIdx.x;
    int t = threadIdx.x;
    float sl = 0.0f, si = 0.0f;
    for (int n = t; n < NTOK; n += 256) sl += g_loadc[(size_t)n * 8 + e];
    for (int a = t; a < NASSIGN; a += 256)
        if (g_route_e[a] == e) si += g_route_g[a];
    __shared__ float shl[256], shi[256];
    shl[t] = sl; shi[t] = si;
    __syncthreads();
    for (int off = 128; off; off >>= 1) {
        if (t < off) { shl[t] += shl[t + off]; shi[t] += shi[t + off]; }
        __syncthreads();
    }
    if (t == 0) { g_load[e] = shl[0]; g_imp[e] = shi[0]; }
}

__global__ void loss_kernel(float* __restrict__ out) {
    if (threadIdx.x != 0 || blockIdx.x != 0) return;
    float mi = 0.0f, ml = 0.0f;
    for (int e = 0; e < NEXP; e++) { mi += g_imp[e]; ml += g_load[e]; }
    mi *= (1.0f / NEXP); ml *= (1.0f / NEXP);
    float vi = 0.0f, vl = 0.0f;
    for (int e = 0; e < NEXP; e++) {
        float di = g_imp[e] - mi;  vi += di * di;
        float dl = g_load[e] - ml; vl += dl * dl;
    }
    vi *= (1.0f / (NEXP - 1)); vl *= (1.0f / (NEXP - 1));
    out[0] = (vi / (mi * mi + 1e-10f) + vl / (ml * ml + 1e-10f)) * 0.01f;
}

// ---------------- fp16 grouped expert GEMM (R15-proven config) ----------------
// CTA tile 128 x 256, k-chunk 64, 8 warps (2m x 4n), warp tile 64x64,
// 4-stage cp.async pipe. Stage: A (16K) | B (32K) = 48KB. 128B rows, XOR-8 swizzle.
#define NSTAGE 4
#define STG (16384u + 256u * 128u)
#define GEMM_SMEM (NSTAGE * (16384 + 256 * 128))

template <int WHICH>
__global__ __launch_bounds__(256, 1) void moe_gemm_f16(const float* __restrict__ bias) {
    constexpr int KD = WHICH ? HDIM : DDIM;
    constexpr int NC = WHICH ? DDIM : HDIM;
    constexpr int NST = KD / 64;

    const int e = blockIdx.z;
    const int count = g_counts[e];
    const int m0 = blockIdx.y * 128;
    if (m0 >= count) return;
    const int c0 = blockIdx.x * 256;

    extern __shared__ char smem[];
    __shared__ int s_a[128];
    const uint32_t sb = smem_to_u32(smem);
    const int t = threadIdx.x;
    const int lane = t & 31, wid = t >> 5;
    const int wm = wid & 1, wn = wid >> 1;

    if (t < 128) {
        int m = m0 + t;
        s_a[t] = (m < count) ? g_perm[e * NTOK + m] : -1;
    }
    __syncthreads();

    const char* Ab = (const char*)(WHICH ? g_hh : g_xh);
    const char* Bb = (const char*)((WHICH ? g_w2t : g_w1t) + ((size_t)e * NC + c0) * KD);

    const char* sA[4]; uint32_t adst[4]; int asz[4];
    #pragma unroll
    for (int i = 0; i < 4; i++) {
        int u = t + 256 * i;
        int r = u >> 3, c = u & 7;
        int a = s_a[r];
        int rowi = (a < 0) ? 0 : (WHICH ? a : (a >> 1));
        sA[i] = Ab + ((size_t)rowi * KD) * 2 + c * 16;
        asz[i] = (a < 0) ? 0 : 16;
        adst[i] = r * 128 + (((uint32_t)(c ^ (r & 7))) << 4);
    }
    const char* sB[8]; uint32_t bdst[8];
    #pragma unroll
    for (int i = 0; i < 8; i++) {
        int u = t + 256 * i;
        int r = u >> 3, c = u & 7;
        sB[i] = Bb + ((size_t)r * KD) * 2 + c * 16;
        bdst[i] = 16384u + r * 128 + (((uint32_t)(c ^ (r & 7))) << 4);
    }

    auto load_stage = [&](int s) {
        uint32_t base = sb + (uint32_t)(s & (NSTAGE - 1)) * STG;
        int koff = s * 128;
        #pragma unroll
        for (int i = 0; i < 4; i++)
            CP_ASYNC16(base + adst[i], sA[i] + koff, asz[i]);
        #pragma unroll
        for (int i = 0; i < 8; i++)
            CP_ASYNC16(base + bdst[i], sB[i] + koff, 16);
        CP_COMMIT();
    };

    uint32_t aoff[4];
    #pragma unroll
    for (int mi = 0; mi < 4; mi++) {
        int row = wm * 64 + mi * 16 + (lane & 15);
        int c = lane >> 4;
        aoff[mi] = row * 128 + (((uint32_t)(c ^ (row & 7))) << 4);
    }
    uint32_t boff[4];
    #pragma unroll
    for (int p = 0; p < 4; p++) {
        int g = lane >> 3;
        int row = wn * 64 + p * 16 + (g >> 1) * 8 + (lane & 7);
        int c = g & 1;
        boff[p] = 16384u + row * 128 + (((uint32_t)(c ^ (row & 7))) << 4);
    }

    float acc[4][8][4];
    #pragma unroll
    for (int i = 0; i < 4; i++)
        #pragma unroll
        for (int j = 0; j < 8; j++)
            #pragma unroll
            for (int k = 0; k < 4; k++) acc[i][j][k] = 0.0f;

    load_stage(0);
    load_stage(1);
    load_stage(2);

    for (int s = 0; s < NST; s++) {
        CP_WAIT2();
        __syncthreads();
        if (s + 3 < NST) load_stage(s + 3);
        else CP_COMMIT();
        uint32_t ab = sb + (uint32_t)(s & (NSTAGE - 1)) * STG;
        #pragma unroll
        for (int ks = 0; ks < 4; ks++) {
            const uint32_t kx = (uint32_t)ks << 5;
            uint32_t Af[4][4], Bf[4][4];
            #pragma unroll
            for (int mi = 0; mi < 4; mi++) ldsm4(Af[mi], ab + (aoff[mi] ^ kx));
            #pragma unroll
            for (int p = 0; p < 4; p++)    ldsm4(Bf[p], ab + (boff[p] ^ kx));
            #pragma unroll
            for (int p = 0; p < 4; p++)
                #pragma unroll
                for (int half = 0; half < 2; half++) {
                    int n = p * 2 + half;
                    #pragma unroll
                    for (int mi = 0; mi < 4; mi++)
                        hmma16816(acc[mi][n], Af[mi], &Bf[p][half * 2]);
                }
        }
    }

    // ---- epilogue ----
    const float* bias_e = bias + (size_t)e * NC + c0;
    int colb = wn * 64 + (lane & 3) * 2;
    float2 bv[8];
    #pragma unroll
    for (int n = 0; n < 8; n++) bv[n] = *(const float2*)(bias_e + colb + n * 8);

    #pragma unroll
    for (int mi = 0; mi < 4; mi++) {
        #pragma unroll
        for (int half = 0; half < 2; half++) {
            int r = wm * 64 + mi * 16 + (lane >> 2) + half * 8;
            int a = s_a[r];
            if (a >= 0) {
                #pragma unroll
                for (int n = 0; n < 8; n++) {
                    float v0 = acc[mi][n][half * 2 + 0] + bv[n].x;
                    float v1 = acc[mi][n][half * 2 + 1] + bv[n].y;
                    size_t col = (size_t)c0 + colb + n * 8;
                    if (WHICH == 0) {
                        v0 = fmaxf(v0, 0.0f); v1 = fmaxf(v1, 0.0f);
                        *(__half2*)(g_hh + (size_t)a * HDIM + col) = __floats2half2_rn(v0, v1);
                    } else {
                        *(__half2*)(g_outb + (size_t)a * DDIM + col) = __floats2half2_rn(v0, v1);
                    }
                }
            }
        }
    }
}

// ---------------- combine (fp16 outb -> fp32 y) ----------------
__global__ void combine_kernel(float* __restrict__ y) {
    int n = blockIdx.x;
    int t = threadIdx.x;
    float gate0 = g_route_g[2 * n];
    float gate1 = g_route_g[2 * n + 1];
    const uint2* o0 = (const uint2*)(g_outb + (size_t)(2 * n) * DDIM);
    const uint2* o1 = (const uint2*)(g_outb + (size_t)(2 * n + 1) * DDIM);
    float4* yp = (float4*)(y + (size_t)n * DDIM);
    uint2 a = o0[t], b = o1[t];
    __half2 a0, a1, b0, b1;
    memcpy(&a0, &a.x, 4); memcpy(&a1, &a.y, 4);
    memcpy(&b0, &b.x, 4); memcpy(&b1, &b.y, 4);
    float2 fa0 = __half22float2(a0), fa1 = __half22float2(a1);
    float2 fb0 = __half22float2(b0), fb1 = __half22float2(b1);
    yp[t] = make_float4(gate0 * fa0.x + gate1 * fb0.x,
                        gate0 * fa0.y + gate1 * fb0.y,
                        gate0 * fa1.x + gate1 * fb1.x,
                        gate0 * fa1.y + gate1 * fb1.y);
}

// ---------------- launch ----------------
extern "C" void kernel_launch(void* const* d_in, const int* in_sizes, int n_in,
                              void* d_out, int out_size) {
    (void)in_sizes; (void)n_in; (void)out_size;
    const float* x  = (const float*)d_in[0];
    const float* nz = (const float*)d_in[1];
    const float* wg = (const float*)d_in[2];
    const float* wn = (const float*)d_in[3];
    const float* W1 = (const float*)d_in[4];
    const float* b1 = (const float*)d_in[5];
    const float* W2 = (const float*)d_in[6];
    const float* b2 = (const float*)d_in[7];
    float* y = (float*)d_out;

    cudaFuncSetAttribute(moe_gemm_f16<0>, cudaFuncAttributeMaxDynamicSharedMemorySize, GEMM_SMEM);
    cudaFuncSetAttribute(moe_gemm_f16<1>, cudaFuncAttributeMaxDynamicSharedMemorySize, GEMM_SMEM);

    zero_counts<<<1, 32>>>();
    prep_kernel<<<PREP_BLKS, 256>>>(x, nz, wg, wn, W1, W2);
    reduce_kernel<<<NEXP, 256>>>();
    loss_kernel<<<1, 1>>>(y + (size_t)NTOK * DDIM);

    moe_gemm_f16<0><<<dim3(HDIM / 256, NASSIGN / 128, NEXP), 256, GEMM_SMEM>>>(b1);
    moe_gemm_f16<1><<<dim3(DDIM / 256, NASSIGN / 128, NEXP), 256, GEMM_SMEM>>>(b2);
    combine_kernel<<<NTOK, 256>>>(y);
}